// round 7
// baseline (speedup 1.0000x reference)
#include <cuda_runtime.h>

#define GRIDA 888
#define GRIDB 1184
#define TPB   256
#define MAXB  1048576

__device__ float4 g_hn[MAXB];               // layer-norm outputs (pass A -> pass B)
__device__ float  g_partials[GRIDA * 16];   // per-block [8 sums, 8 sumsq]
__device__ float  g_final[12];              // [0:8) sc, [8:11) bp
__device__ unsigned g_done = 0;             // self-resetting ticket (replay-safe)

__device__ __forceinline__ float ex2f(float x) {
    float y; asm("ex2.approx.ftz.f32 %0, %1;" : "=f"(y) : "f"(x)); return y;
}
__device__ __forceinline__ float sin_fast(float x) {
    float y; asm("sin.approx.ftz.f32 %0, %1;" : "=f"(y) : "f"(x)); return y;
}

// =======================  PASS A  =======================
__global__ __launch_bounds__(TPB, 3)
void passA(const float* __restrict__ xg,
           const float* __restrict__ W1, const float* __restrict__ b1,
           const float* __restrict__ gam, const float* __restrict__ bet,
           const float* __restrict__ mIn, const float* __restrict__ th,
           const float* __restrict__ g2, const float* __restrict__ bt2,
           const float* __restrict__ W2, const float* __restrict__ b2,
           int n, int rpb)
{
    __shared__ float prm[64];
    __shared__ float stage[8 * 352];   // 8 warps x 32 rows x 11 floats (pad -> conflict-free)
    __shared__ int   sflag;

    const int tid = threadIdx.x, bid = blockIdx.x;
    const int wid = tid >> 5, lane = tid & 31;

    if      (tid < 30) prm[tid] = W1[tid];
    else if (tid < 33) prm[tid] = b1[tid - 30];
    else if (tid < 36) prm[tid] = gam[tid - 33];
    else if (tid < 39) prm[tid] = bet[tid - 36];
    else if (tid < 45) prm[tid] = mIn[tid - 39];
    else if (tid < 51) { const float t = th[tid - 45];
                         prm[tid] = -1.4426950408889634f / (2.0f * t * t); }
    __syncthreads();

    float w1[30], bb1[3], gm[3], bt[3], mv[6], c2[6];
#pragma unroll
    for (int i = 0; i < 30; i++) w1[i] = prm[i];
#pragma unroll
    for (int i = 0; i < 3; i++) { bb1[i] = prm[30 + i]; gm[i] = prm[33 + i]; bt[i] = prm[36 + i]; }
#pragma unroll
    for (int i = 0; i < 6; i++) { mv[i] = prm[39 + i]; c2[i] = prm[45 + i]; }

    const int row0 = bid * rpb;
    const int rEnd = min(row0 + rpb, n);
    float* buf = stage + wid * 352;
    const float C2 = 0.99999f * 0.99999f;
    const int iters = (rpb + TPB - 1) / TPB;

    float acc[16];
#pragma unroll
    for (int i = 0; i < 16; i++) acc[i] = 0.f;

    for (int k = 0; k < iters; k++) {
        const int warpBase = row0 + k * TPB + wid * 32;
        if (warpBase < rEnd) {
            const float* src = xg + (size_t)warpBase * 10;
            const int lim = (rEnd - warpBase) * 10;
#pragma unroll
            for (int j = 0; j < 10; j++) {
                const int idx = j * 32 + lane;
                if (idx < lim) buf[(idx / 10) * 11 + (idx % 10)] = src[idx];
            }
        }
        __syncwarp();
        const int r = warpBase + lane;
        if (r < rEnd) {
            float xv[10];
#pragma unroll
            for (int j = 0; j < 10; j++) xv[j] = buf[lane * 11 + j];

            float h[3];
#pragma unroll
            for (int q = 0; q < 3; q++) {
                float a = bb1[q];
#pragma unroll
                for (int c = 0; c < 10; c++) a = fmaf(xv[c], w1[q * 10 + c], a);
                h[q] = a;
            }
            const float mu = (h[0] + h[1] + h[2]) * (1.0f / 3.0f);
            const float d0 = h[0] - mu, d1 = h[1] - mu, d2 = h[2] - mu;
            const float var = (d0 * d0 + d1 * d1 + d2 * d2) * (1.0f / 3.0f);
            const float rn = rsqrtf(var + 1e-5f);
            const float hn0 = fmaf(d0 * rn, gm[0], bt[0]);
            const float hn1 = fmaf(d1 * rn, gm[1], bt[1]);
            const float hn2 = fmaf(d2 * rn, gm[2], bt[2]);
            g_hn[r] = make_float4(hn0, hn1, hn2, 0.f);

            float p[6];
#pragma unroll
            for (int kk = 0; kk < 6; kk++) {
                const float hq = (kk < 2) ? hn0 : (kk < 4) ? hn1 : hn2;
                const float a = hq - mv[kk];
                const float f = ex2f(a * a * c2[kk]);
                const float pv = fminf(f + 1e-16f, C2);
                p[kk] = (kk < 2) ? pv : (1.0f - pv);
            }
            const float w00 = p[2] * p[4], w01 = p[2] * p[5];
            const float w10 = p[3] * p[4], w11 = p[3] * p[5];
            float o[8];
            o[0] = p[0] * w00; o[1] = p[0] * w01; o[2] = p[0] * w10; o[3] = p[0] * w11;
            o[4] = p[1] * w00; o[5] = p[1] * w01; o[6] = p[1] * w10; o[7] = p[1] * w11;
#pragma unroll
            for (int c = 0; c < 8; c++) {
                acc[c] += o[c];
                acc[8 + c] = fmaf(o[c], o[c], acc[8 + c]);
            }
        }
        __syncwarp();
    }

    // deterministic block reduction -> g_partials
    __syncthreads();
    float* red = stage;
#pragma unroll
    for (int kk = 0; kk < 16; kk++) {
        float v = acc[kk];
#pragma unroll
        for (int off = 16; off; off >>= 1)
            v += __shfl_down_sync(0xffffffffu, v, off);
        if (lane == 0) red[wid * 16 + kk] = v;
    }
    __syncthreads();
    if (tid < 16) {
        float s = 0.f;
#pragma unroll
        for (int w = 0; w < 8; w++) s += red[w * 16 + tid];
        g_partials[bid * 16 + tid] = s;
    }

    // ---- last block folds partials and finalizes BN constants ----
    if (tid == 0) {
        __threadfence();
        const unsigned t = atomicAdd(&g_done, 1u);
        sflag = (t == GRIDA - 1u) ? 1 : 0;
    }
    __syncthreads();
    if (sflag) {
        float* red2 = stage + 256;   // separate scratch region
        {
            const int met = tid & 15, ch = tid >> 4;
            float s = 0.f;
            for (int b = ch; b < GRIDA; b += 16)
                s += __ldcg(&g_partials[b * 16 + met]);
            red2[tid] = s;
        }
        __syncthreads();
        if (tid < 16) {
            float s = 0.f;
#pragma unroll
            for (int w = 0; w < 16; w++) s += red2[w * 16 + tid];
            stage[tid] = s;           // totals: [0:8) sums, [8:16) sumsq
        }
        __syncthreads();
        if (tid < 8) {
            const float invB = 1.0f / (float)n;
            const float muv = stage[tid] * invB;
            const float msq = stage[8 + tid] * invB;
            const float var = msq - muv * muv;
            const float sc = g2[tid] * rsqrtf(var + 1e-5f);
            g_final[tid] = sc;
            stage[32 + tid] = bt2[tid] - muv * sc;   // t2
        }
        __syncthreads();
        if (tid < 3) {
            float a = b2[tid];
#pragma unroll
            for (int c = 0; c < 8; c++) a = fmaf(stage[32 + c], W2[tid * 8 + c], a);
            g_final[8 + tid] = a;
        }
        if (tid == 0) g_done = 0;    // reset for next graph replay
    }
}

// =======================  PASS B  =======================
__global__ __launch_bounds__(TPB, 4)
void passB(float* __restrict__ outg,
           const float* __restrict__ mIn, const float* __restrict__ th,
           const float* __restrict__ W2,
           int n)
{
    __shared__ float prm[52];   // m 0..5, c2 6..11, W2 12..35, sc 36..43, bp 44..46

    const int tid = threadIdx.x, bid = blockIdx.x;

    if      (tid < 6)  prm[tid] = mIn[tid];
    else if (tid < 12) { const float t = th[tid - 6];
                         prm[tid] = -1.4426950408889634f / (2.0f * t * t); }
    else if (tid < 36) prm[tid] = W2[tid - 12];        // rows 0..2 of W2
    else if (tid < 44) prm[tid] = g_final[tid - 36];   // sc
    else if (tid < 47) prm[tid] = g_final[8 + tid - 44]; // bp
    __syncthreads();

    // registers: W2 pre-scaled by sc  ->  lg_i = bp_i + sum_c o_c * w2p[i*8+c]
    float mv[6], c2[6], w2p[24], bp[3];
#pragma unroll
    for (int i = 0; i < 6; i++) { mv[i] = prm[i]; c2[i] = prm[6 + i]; }
#pragma unroll
    for (int i = 0; i < 3; i++) {
        bp[i] = prm[44 + i];
#pragma unroll
        for (int c = 0; c < 8; c++) w2p[i * 8 + c] = prm[12 + i * 8 + c] * prm[36 + c];
    }

    const float C2 = 0.99999f * 0.99999f;
    const int NTB = GRIDB * TPB;
    const int iters = (n + NTB - 1) / NTB;

    for (int k = 0; k < iters; k++) {
        const int r = bid * TPB + tid + k * NTB;
        if (r < n) {
            const float4 hv = g_hn[r];
            float p[6];
#pragma unroll
            for (int kk = 0; kk < 6; kk++) {
                const float hq = (kk < 2) ? hv.x : (kk < 4) ? hv.y : hv.z;
                const float a = hq - mv[kk];
                const float f = ex2f(a * a * c2[kk]);
                const float pv = fminf(f + 1e-16f, C2);
                p[kk] = (kk < 2) ? pv : (1.0f - pv);
            }
            const float w00 = p[2] * p[4], w01 = p[2] * p[5];
            const float w10 = p[3] * p[4], w11 = p[3] * p[5];
            float o[8];
            o[0] = p[0] * w00; o[1] = p[0] * w01; o[2] = p[0] * w10; o[3] = p[0] * w11;
            o[4] = p[1] * w00; o[5] = p[1] * w01; o[6] = p[1] * w10; o[7] = p[1] * w11;
            float lg[3];
#pragma unroll
            for (int i = 0; i < 3; i++) {
                float a = bp[i];
#pragma unroll
                for (int c = 0; c < 8; c++) a = fmaf(o[c], w2p[i * 8 + c], a);
                lg[i] = a;
            }
            const float sg0 = sin_fast(lg[0] * 0.5f);
            const float sg1 = sin_fast(lg[1] * 0.5f);
            const float sg2 = sin_fast(lg[2] * 0.5f);
            const float pq0 = sg0 * sg0, pq1 = sg1 * sg1, pq2 = sg2 * sg2;
            const float cq0 = 1.f - pq0, cq1 = 1.f - pq1, cq2 = 1.f - pq2;
            const float tt = cq1 * cq2;
            float* dst = outg + (size_t)r * 3;
            dst[0] = cq0 * tt;
            dst[1] = pq0 * tt;
            dst[2] = cq0 * (pq1 * cq2);
        }
    }
}

extern "C" void kernel_launch(void* const* d_in, const int* in_sizes, int n_in,
                              void* d_out, int out_size)
{
    const float* x = (const float*)d_in[0];
    const int n = in_sizes[0] / 10;
    const int rpb = (n + GRIDA - 1) / GRIDA;

    passA<<<GRIDA, TPB>>>(x,
        (const float*)d_in[1], (const float*)d_in[2], (const float*)d_in[3],
        (const float*)d_in[4], (const float*)d_in[5], (const float*)d_in[6],
        (const float*)d_in[7], (const float*)d_in[8], (const float*)d_in[9],
        (const float*)d_in[10], n, rpb);

    passB<<<GRIDB, TPB>>>((float*)d_out,
        (const float*)d_in[5], (const float*)d_in[6], (const float*)d_in[9], n);
}

// round 8
// speedup vs baseline: 1.5274x; 1.5274x over previous
#include <cuda_runtime.h>

#define GRIDA 592
#define GRIDB 1480
#define TPB   256
#define MAXB  1048576

// cP layout: [0:30) W1, [30:33) b1, [33:36) gamma, [36:39) beta,
// [39:45) m, [45:51) c2 (pre-folded -log2e/(2 th^2)), [51:59) g2,
// [59:67) bt2, [67:147) W2, [147:150) b2[0:3)
__constant__ float cP[150];
__device__ float g_pack[150];

__device__ float4 g_hn[MAXB];               // layer-norm outputs (A -> B)
__device__ float  g_partials[GRIDA * 16];   // per-block [8 sums, 8 sumsq]
__device__ float  g_final[11];              // [0:8) sc, [8:11) bp
__device__ unsigned g_done = 0;             // self-resetting ticket (replay-safe)

#define W1c(i)  cP[(i)]
#define B1c(i)  cP[30 + (i)]
#define GAMc(i) cP[33 + (i)]
#define BETc(i) cP[36 + (i)]
#define Mc(i)   cP[39 + (i)]
#define C2c(i)  cP[45 + (i)]
#define G2c(i)  cP[51 + (i)]
#define BT2c(i) cP[59 + (i)]
#define W2c(i)  cP[67 + (i)]
#define B2c(i)  cP[147 + (i)]

__device__ __forceinline__ float ex2f(float x) {
    float y; asm("ex2.approx.ftz.f32 %0, %1;" : "=f"(y) : "f"(x)); return y;
}
__device__ __forceinline__ float sin_fast(float x) {
    float y; asm("sin.approx.ftz.f32 %0, %1;" : "=f"(y) : "f"(x)); return y;
}

__global__ void pack_kernel(const float* __restrict__ W1, const float* __restrict__ b1,
                            const float* __restrict__ gam, const float* __restrict__ bet,
                            const float* __restrict__ m, const float* __restrict__ th,
                            const float* __restrict__ g2, const float* __restrict__ bt2,
                            const float* __restrict__ W2, const float* __restrict__ b2)
{
    const int t = threadIdx.x;
    if      (t < 30)  g_pack[t] = W1[t];
    else if (t < 33)  g_pack[t] = b1[t - 30];
    else if (t < 36)  g_pack[t] = gam[t - 33];
    else if (t < 39)  g_pack[t] = bet[t - 36];
    else if (t < 45)  g_pack[t] = m[t - 39];
    else if (t < 51)  { const float v = th[t - 45];
                        g_pack[t] = -1.4426950408889634f / (2.0f * v * v); }
    else if (t < 59)  g_pack[t] = g2[t - 51];
    else if (t < 67)  g_pack[t] = bt2[t - 59];
    else if (t < 147) g_pack[t] = W2[t - 67];
    else if (t < 150) g_pack[t] = b2[t - 147];
}

// =======================  PASS A  =======================
__global__ __launch_bounds__(TPB, 4)
void passA(const float* __restrict__ xg, int n)
{
    __shared__ float red[128];     // 8 warps x 16
    __shared__ float red2[256];
    __shared__ float tot[16];
    __shared__ float t2s[8];
    __shared__ int   sflag;

    const int tid = threadIdx.x, bid = blockIdx.x;
    const int wid = tid >> 5, lane = tid & 31;
    const int NTOT = GRIDA * TPB;
    const float C2 = 0.99999f * 0.99999f;

    float acc[16];
#pragma unroll
    for (int i = 0; i < 16; i++) acc[i] = 0.f;

    for (int r = bid * TPB + tid; r < n; r += NTOT) {
        const float2* xp = (const float2*)(xg + (size_t)r * 10);
        const float2 v0 = xp[0], v1 = xp[1], v2 = xp[2], v3 = xp[3], v4 = xp[4];
        const float xv[10] = {v0.x, v0.y, v1.x, v1.y, v2.x,
                              v2.y, v3.x, v3.y, v4.x, v4.y};
        float h[3];
#pragma unroll
        for (int q = 0; q < 3; q++) {
            float a = B1c(q);
#pragma unroll
            for (int c = 0; c < 10; c++) a = fmaf(xv[c], W1c(q * 10 + c), a);
            h[q] = a;
        }
        const float mu = (h[0] + h[1] + h[2]) * (1.0f / 3.0f);
        const float d0 = h[0] - mu, d1 = h[1] - mu, d2 = h[2] - mu;
        const float var = (d0 * d0 + d1 * d1 + d2 * d2) * (1.0f / 3.0f);
        const float rn = rsqrtf(var + 1e-5f);
        const float hn0 = fmaf(d0 * rn, GAMc(0), BETc(0));
        const float hn1 = fmaf(d1 * rn, GAMc(1), BETc(1));
        const float hn2 = fmaf(d2 * rn, GAMc(2), BETc(2));
        g_hn[r] = make_float4(hn0, hn1, hn2, 0.f);

        float p[6];
#pragma unroll
        for (int kk = 0; kk < 6; kk++) {
            const float hq = (kk < 2) ? hn0 : (kk < 4) ? hn1 : hn2;
            const float a = hq - Mc(kk);
            const float f = ex2f(a * a * C2c(kk));
            const float pv = fminf(f + 1e-16f, C2);
            p[kk] = (kk < 2) ? pv : (1.0f - pv);
        }
        const float w00 = p[2] * p[4], w01 = p[2] * p[5];
        const float w10 = p[3] * p[4], w11 = p[3] * p[5];
        float o[8];
        o[0] = p[0] * w00; o[1] = p[0] * w01; o[2] = p[0] * w10; o[3] = p[0] * w11;
        o[4] = p[1] * w00; o[5] = p[1] * w01; o[6] = p[1] * w10; o[7] = p[1] * w11;
#pragma unroll
        for (int c = 0; c < 8; c++) {
            acc[c] += o[c];
            acc[8 + c] = fmaf(o[c], o[c], acc[8 + c]);
        }
    }

    // deterministic block reduction -> g_partials
#pragma unroll
    for (int kk = 0; kk < 16; kk++) {
        float v = acc[kk];
#pragma unroll
        for (int off = 16; off; off >>= 1)
            v += __shfl_down_sync(0xffffffffu, v, off);
        if (lane == 0) red[wid * 16 + kk] = v;
    }
    __syncthreads();
    if (tid < 16) {
        float s = 0.f;
#pragma unroll
        for (int w = 0; w < 8; w++) s += red[w * 16 + tid];
        g_partials[bid * 16 + tid] = s;
    }

    // ---- last block folds partials -> g_final ----
    if (tid == 0) {
        __threadfence();
        const unsigned t = atomicAdd(&g_done, 1u);
        sflag = (t == GRIDA - 1u) ? 1 : 0;
    }
    __syncthreads();
    if (sflag) {
        {
            const int met = tid & 15, ch = tid >> 4;
            float s = 0.f;
            for (int b = ch; b < GRIDA; b += 16)
                s += __ldcg(&g_partials[b * 16 + met]);
            red2[tid] = s;
        }
        __syncthreads();
        if (tid < 16) {
            float s = 0.f;
#pragma unroll
            for (int w = 0; w < 16; w++) s += red2[w * 16 + tid];
            tot[tid] = s;
        }
        __syncthreads();
        if (tid < 8) {
            const float invB = 1.0f / (float)n;
            const float muv = tot[tid] * invB;
            const float msq = tot[8 + tid] * invB;
            const float var = msq - muv * muv;
            const float sc = G2c(tid) * rsqrtf(var + 1e-5f);
            g_final[tid] = sc;
            t2s[tid] = BT2c(tid) - muv * sc;
        }
        __syncthreads();
        if (tid < 3) {
            float a = B2c(tid);
#pragma unroll
            for (int c = 0; c < 8; c++) a = fmaf(t2s[c], W2c(tid * 8 + c), a);
            g_final[8 + tid] = a;
        }
        if (tid == 0) g_done = 0;   // reset for next replay
    }
}

// =======================  PASS B  =======================
__global__ __launch_bounds__(TPB, 5)
void passB(float* __restrict__ outg, int n)
{
    __shared__ float sf[11];
    const int tid = threadIdx.x, bid = blockIdx.x;

    if (tid < 11) sf[tid] = g_final[tid];
    __syncthreads();

    float sc[8], bp[3];
#pragma unroll
    for (int i = 0; i < 8; i++) sc[i] = sf[i];
#pragma unroll
    for (int i = 0; i < 3; i++) bp[i] = sf[8 + i];

    const float C2 = 0.99999f * 0.99999f;
    const int NTB = GRIDB * TPB;

    for (int r = bid * TPB + tid; r < n; r += NTB) {
        const float4 hv = g_hn[r];
        float p[6];
#pragma unroll
        for (int kk = 0; kk < 6; kk++) {
            const float hq = (kk < 2) ? hv.x : (kk < 4) ? hv.y : hv.z;
            const float a = hq - Mc(kk);
            const float f = ex2f(a * a * C2c(kk));
            const float pv = fminf(f + 1e-16f, C2);
            p[kk] = (kk < 2) ? pv : (1.0f - pv);
        }
        const float w00 = p[2] * p[4], w01 = p[2] * p[5];
        const float w10 = p[3] * p[4], w11 = p[3] * p[5];
        float u[8];
        u[0] = p[0] * w00 * sc[0]; u[1] = p[0] * w01 * sc[1];
        u[2] = p[0] * w10 * sc[2]; u[3] = p[0] * w11 * sc[3];
        u[4] = p[1] * w00 * sc[4]; u[5] = p[1] * w01 * sc[5];
        u[6] = p[1] * w10 * sc[6]; u[7] = p[1] * w11 * sc[7];
        float lg[3];
#pragma unroll
        for (int i = 0; i < 3; i++) {
            float a = bp[i];
#pragma unroll
            for (int c = 0; c < 8; c++) a = fmaf(u[c], W2c(i * 8 + c), a);
            lg[i] = a;
        }
        const float sg0 = sin_fast(lg[0] * 0.5f);
        const float sg1 = sin_fast(lg[1] * 0.5f);
        const float sg2 = sin_fast(lg[2] * 0.5f);
        const float pq0 = sg0 * sg0, pq1 = sg1 * sg1, pq2 = sg2 * sg2;
        const float cq0 = 1.f - pq0, cq1 = 1.f - pq1, cq2 = 1.f - pq2;
        const float tt = cq1 * cq2;
        float* dst = outg + (size_t)r * 3;
        dst[0] = cq0 * tt;
        dst[1] = pq0 * tt;
        dst[2] = cq0 * (pq1 * cq2);
    }
}

extern "C" void kernel_launch(void* const* d_in, const int* in_sizes, int n_in,
                              void* d_out, int out_size)
{
    const float* x = (const float*)d_in[0];
    const int n = in_sizes[0] / 10;

    pack_kernel<<<1, 160, 0, 0>>>(
        (const float*)d_in[1], (const float*)d_in[2], (const float*)d_in[3],
        (const float*)d_in[4], (const float*)d_in[5], (const float*)d_in[6],
        (const float*)d_in[7], (const float*)d_in[8], (const float*)d_in[9],
        (const float*)d_in[10]);

    void* packAddr = nullptr;
    cudaGetSymbolAddress(&packAddr, g_pack);
    cudaMemcpyToSymbolAsync(cP, packAddr, 150 * sizeof(float), 0,
                            cudaMemcpyDeviceToDevice, 0);

    passA<<<GRIDA, TPB>>>(x, n);
    passB<<<GRIDB, TPB>>>((float*)d_out, n);
}